// round 14
// baseline (speedup 1.0000x reference)
#include <cuda_runtime.h>

// Histogram2d: x[32,16384,64] f32 in [0,1) -> hist[32,128,64] * weights[128,64]
//
// Hist: 512-thread blocks (2 feature-halves x 8 row-offsets), per-thread
// private u8 histograms in SMEM, bank-aligned (lane l always hits bank l ->
// conflict-free RMWs). Grid = 444 blocks = 148 SMs x occ 3, perfectly
// balanced: batches 0..27 get 14 chunks, batches 28..31 get 13 chunks
// (all chunk sizes %8 == 0; iters <= 164 -> u8 provably safe).
// Dump: u16x4-in-u64 packed REDG atomicAdd into a 512KB per-batch
// accumulator (carry-free: each u16 field <= 16384 < 2^16). Finalize
// applies weights and restores the accumulator to zero for graph replay.

constexpr int B = 32, S = 16384, F = 64, BINS = 128;
constexpr int THREADS = 512;           // 16 warps: fh = w&1, soff = w>>1 (0..7)
constexpr int NBLOCKS = 444;           // 148 SMs x 3 resident blocks, one wave
// smem: 16 warps x 1024 words. word(w, m, l) = w*1024 + m*32 + l  (bank = l)
constexpr int SMEM_BYTES = 16 * 1024 * 4;          // 65536 B -> 3 blocks/SM (48 warps)

// u64 accumulators: word W64 = m*64 + f holds bins (4m..4m+3) of feature f:
// lo32 = bins(4m,4m+1) u16x2, hi32 = bins(4m+2,4m+3) u16x2.
constexpr int P64 = (BINS / 4) * F;                // 2048 u64 per batch
__device__ __align__(16) unsigned long long g_accum[(size_t)B * P64];  // 512 KB, starts 0

__global__ __launch_bounds__(THREADS, 3)
void hist_kernel(const float* __restrict__ x) {
    extern __shared__ unsigned int sh[];
    const int tid = threadIdx.x;
    const int w = tid >> 5, l = tid & 31;

    // zero own histogram: word (w, m, l) -> bank l, conflict-free, private
#pragma unroll
    for (int m = 0; m < 32; m++) sh[(w << 10) + (m << 5) + l] = 0u;

    unsigned char* sb = reinterpret_cast<unsigned char*>(sh);
    const unsigned int tbase = (w << 12) + (l << 2);   // byte base of this lane's hist

    const int fh = w & 1;        // feature half: 0 -> f 0..31, 1 -> f 32..63
    const int soff = w >> 1;     // row offset mod 8
    const int f = fh * 32 + l;

    // balanced chunk map: 444 = 28 batches x 14 chunks + 4 batches x 13
    const int cid = blockIdx.x;
    const int b = cid & 31, c = cid >> 5;    // c=13 only occurs for b<28
    const int nc   = (b < 28) ? 14 : 13;
    const int base_rows = (b < 28) ? 1168 : 1256;   // both %8 == 0
    const int row0 = c * base_rows;
    const int rows = (c == nc - 1) ? (S - row0) : base_rows;  // 1200 / 1312 tails
    const int iters = rows >> 3;             // 146..164 <= 255 -> u8 safe
    const float* xb = x + (((size_t)b * S + row0 + soff) * F + f);

    constexpr int U = 8;                     // load-ahead for MLP
    int i = 0;
#pragma unroll 1
    for (; i + U <= iters; i += U) {
        float v[U];
#pragma unroll
        for (int u = 0; u < U; u++)
            v[u] = __ldcs(xb + (size_t)(i + u) * (8 * F));
#pragma unroll
        for (int u = 0; u < U; u++) {
            // exact trunc(v*128): RZ-add truncates mantissa; bin bits = [16:23)
            const unsigned int bits = __float_as_uint(__fadd_rz(v[u], 1.0f));
            // byte offset ((bin>>2)<<7) | (bin&3): keeps this lane in bank l
            const unsigned int off = (((bits >> 18) & 31u) << 7) | ((bits >> 16) & 3u);
            sb[tbase + off] = (unsigned char)(sb[tbase + off] + 1);
        }
    }
#pragma unroll 1
    for (; i < iters; i++) {                 // tail (<8 iters)
        const unsigned int bits =
            __float_as_uint(__fadd_rz(__ldcs(xb + (size_t)i * (8 * F)), 1.0f));
        const unsigned int off = (((bits >> 18) & 31u) << 7) | ((bits >> 16) & 3u);
        sb[tbase + off] = (unsigned char)(sb[tbase + off] + 1);
    }
    __syncthreads();

    // Intra-block reduction over 8 row-offsets (dp4a byte extraction),
    // one u64 REDG per (4-bin group, feature): coalesced, fire-and-forget.
    // Per-bin block partial <= 8*164 = 1312; batch total <= 16384 < 2^16.
    unsigned long long* outp = g_accum + (size_t)b * P64;
#pragma unroll
    for (int k = 0; k < 4; k++) {
        const int u = tid + THREADS * k;     // 0..2047
        const int fo = u & 63;
        const int m  = u >> 6;               // -> bins 4m..4m+3
        const int fh2 = fo >> 5, fl = fo & 31;
        unsigned int s0 = 0, s1 = 0, s2 = 0, s3 = 0;
#pragma unroll
        for (int s = 0; s < 8; s++) {
            const unsigned int v = sh[((2 * s + fh2) << 10) + (m << 5) + fl];
            s0 = __dp4a(v, 0x00000001u, s0);
            s1 = __dp4a(v, 0x00000100u, s1);
            s2 = __dp4a(v, 0x00010000u, s2);
            s3 = __dp4a(v, 0x01000000u, s3);
        }
        const unsigned long long val =
            (unsigned long long)(s0 | (s1 << 16)) |
            ((unsigned long long)(s2 | (s3 << 16)) << 32);
        atomicAdd(&outp[m * F + fo], val);   // RED.E.ADD.64, no return
    }
}

__global__ __launch_bounds__(256)
void finalize_kernel(const float* __restrict__ wts, float* __restrict__ out) {
    // One thread per u64 accumulator word: B*2048 = 65536 threads, 256 blocks.
    const int idx = blockIdx.x * 256 + threadIdx.x;
    const int b   = idx >> 11;
    const int W64 = idx & 2047;              // m*64 + fo
    const int m   = W64 >> 6;                // bins 4m..4m+3
    const int fo  = W64 & 63;

    uint2* pa = reinterpret_cast<uint2*>(g_accum) + idx;   // coalesced
    const uint2 v = *pa;
    *pa = make_uint2(0u, 0u);                // restore zero for next replay

    const float* wb = wts + (4 * m) * F + fo;
    float* ob = out + ((size_t)b * BINS + 4 * m) * F + fo;
    ob[0 * F] = (float)(v.x & 0xFFFFu) * wb[0 * F];
    ob[1 * F] = (float)(v.x >> 16)     * wb[1 * F];
    ob[2 * F] = (float)(v.y & 0xFFFFu) * wb[2 * F];
    ob[3 * F] = (float)(v.y >> 16)     * wb[3 * F];
}

extern "C" void kernel_launch(void* const* d_in, const int* in_sizes, int n_in,
                              void* d_out, int out_size) {
    const float* x   = (const float*)d_in[0];
    const float* wts = (const float*)d_in[1];
    float* out = (float*)d_out;

    cudaFuncSetAttribute(hist_kernel, cudaFuncAttributeMaxDynamicSharedMemorySize, SMEM_BYTES);

    hist_kernel<<<NBLOCKS, THREADS, SMEM_BYTES>>>(x);
    finalize_kernel<<<(B * P64) / 256, 256>>>(wts, out);
}

// round 15
// speedup vs baseline: 1.0481x; 1.0481x over previous
#include <cuda_runtime.h>

// Histogram2d: x[32,16384,64] f32 in [0,1) -> hist[32,128,64] * weights[128,64]
//
// Champion configuration (round 12, 33.25us), restored after two regressing
// excursions (PDL: +1.0us; re-gridding to 444 variable-weight blocks: +2.3us).
//
// Hist: 512-thread blocks (2 feature-halves x 8 row-offsets), NCHUNK=13 ->
// 416 blocks, single wave at occ 3 (48 warps/SM — proven necessary by the
// occupancy-halving probes of rounds 9 and 11). Per-thread private u8
// histograms in SMEM, bank-aligned: word(w,m,l) = w*1024 + m*32 + l keeps
// every RMW of lane l in bank l -> conflict-free by construction, zero
// atomics in the mainloop. Binning via RZ-add bit trick (exact trunc(v*128)).
// Dump: intra-block dp4a reduction over the 8 row-offsets, then one
// u16x4-in-u64 packed REDG atomicAdd per (4-bin group, feature) into a
// 512KB per-batch accumulator. Carry-free proof: per-bin block partial
// <= 8*160 = 1280, per-bin batch total <= 16384 < 2^16, low u32 < 2^32.
// Finalize applies weights and restores the accumulator to zero so every
// graph replay re-enters with zeroed state (deterministic, no memset node).

constexpr int B = 32, S = 16384, F = 64, BINS = 128;
constexpr int NCHUNK = 13;             // 12*1280 + 1024 = 16384
constexpr int CHUNK = 1280;            // iters = 160/128 (<=255 u8-safe, %8==0)
constexpr int THREADS = 512;           // 16 warps: fh = w&1, soff = w>>1 (0..7)
// smem: 16 warps x 1024 words. word(w, m, l) = w*1024 + m*32 + l  (bank = l)
constexpr int SMEM_BYTES = 16 * 1024 * 4;          // 65536 B -> 3 blocks/SM (48 warps)

// u64 accumulators: word W64 = m*64 + f holds bins (4m..4m+3) of feature f:
// lo32 = bins(4m,4m+1) u16x2, hi32 = bins(4m+2,4m+3) u16x2.
constexpr int P64 = (BINS / 4) * F;                // 2048 u64 per batch
__device__ __align__(16) unsigned long long g_accum[(size_t)B * P64];  // 512 KB, starts 0

__global__ __launch_bounds__(THREADS, 3)
void hist_kernel(const float* __restrict__ x) {
    extern __shared__ unsigned int sh[];
    const int tid = threadIdx.x;
    const int w = tid >> 5, l = tid & 31;

    // zero own histogram: word (w, m, l) -> bank l, conflict-free, private
#pragma unroll
    for (int m = 0; m < 32; m++) sh[(w << 10) + (m << 5) + l] = 0u;

    unsigned char* sb = reinterpret_cast<unsigned char*>(sh);
    const unsigned int tbase = (w << 12) + (l << 2);   // byte base of this lane's hist

    const int fh = w & 1;        // feature half: 0 -> f 0..31, 1 -> f 32..63
    const int soff = w >> 1;     // row offset mod 8
    const int f = fh * 32 + l;
    const int b = blockIdx.y, c = blockIdx.x;

    const int row0 = c * CHUNK;
    const int rows = min(CHUNK, S - row0);   // 1280 or 1024
    const int iters = rows >> 3;             // 160 or 128 (%8==0) -> u8 safe
    const float* base = x + (((size_t)b * S + row0 + soff) * F + f);

    constexpr int U = 8;                     // load-ahead for MLP
#pragma unroll 1
    for (int i = 0; i < iters; i += U) {
        float v[U];
#pragma unroll
        for (int u = 0; u < U; u++)
            v[u] = __ldcs(base + (size_t)(i + u) * (8 * F));
#pragma unroll
        for (int u = 0; u < U; u++) {
            // exact trunc(v*128): RZ-add truncates mantissa; bin bits = [16:23)
            const unsigned int bits = __float_as_uint(__fadd_rz(v[u], 1.0f));
            // byte offset ((bin>>2)<<7) | (bin&3): keeps this lane in bank l
            const unsigned int off = (((bits >> 18) & 31u) << 7) | ((bits >> 16) & 3u);
            sb[tbase + off] = (unsigned char)(sb[tbase + off] + 1);
        }
    }
    __syncthreads();

    // Intra-block reduction over 8 row-offsets (dp4a byte extraction),
    // one u64 REDG per (4-bin group, feature): coalesced, fire-and-forget.
    // smem loads hit bank fl = lane -> conflict-free.
    unsigned long long* outp = g_accum + (size_t)b * P64;
#pragma unroll
    for (int k = 0; k < 4; k++) {
        const int u = tid + THREADS * k;     // 0..2047
        const int fo = u & 63;
        const int m  = u >> 6;               // -> bins 4m..4m+3
        const int fh2 = fo >> 5, fl = fo & 31;
        unsigned int s0 = 0, s1 = 0, s2 = 0, s3 = 0;
#pragma unroll
        for (int s = 0; s < 8; s++) {
            const unsigned int v = sh[((2 * s + fh2) << 10) + (m << 5) + fl];
            s0 = __dp4a(v, 0x00000001u, s0);
            s1 = __dp4a(v, 0x00000100u, s1);
            s2 = __dp4a(v, 0x00010000u, s2);
            s3 = __dp4a(v, 0x01000000u, s3);
        }
        const unsigned long long val =
            (unsigned long long)(s0 | (s1 << 16)) |
            ((unsigned long long)(s2 | (s3 << 16)) << 32);
        atomicAdd(&outp[m * F + fo], val);   // RED.E.ADD.64, no return
    }
}

__global__ __launch_bounds__(256)
void finalize_kernel(const float* __restrict__ wts, float* __restrict__ out) {
    // One thread per u64 accumulator word: B*2048 = 65536 threads, 256 blocks.
    const int idx = blockIdx.x * 256 + threadIdx.x;
    const int b   = idx >> 11;
    const int W64 = idx & 2047;              // m*64 + fo
    const int m   = W64 >> 6;                // bins 4m..4m+3
    const int fo  = W64 & 63;

    uint2* pa = reinterpret_cast<uint2*>(g_accum) + idx;   // coalesced
    const uint2 v = *pa;
    *pa = make_uint2(0u, 0u);                // restore zero for next replay

    const float* wb = wts + (4 * m) * F + fo;
    float* ob = out + ((size_t)b * BINS + 4 * m) * F + fo;
    ob[0 * F] = (float)(v.x & 0xFFFFu) * wb[0 * F];
    ob[1 * F] = (float)(v.x >> 16)     * wb[1 * F];
    ob[2 * F] = (float)(v.y & 0xFFFFu) * wb[2 * F];
    ob[3 * F] = (float)(v.y >> 16)     * wb[3 * F];
}

extern "C" void kernel_launch(void* const* d_in, const int* in_sizes, int n_in,
                              void* d_out, int out_size) {
    const float* x   = (const float*)d_in[0];
    const float* wts = (const float*)d_in[1];
    float* out = (float*)d_out;

    cudaFuncSetAttribute(hist_kernel, cudaFuncAttributeMaxDynamicSharedMemorySize, SMEM_BYTES);

    dim3 grid(NCHUNK, B);   // 13 x 32 = 416 blocks, single wave at occ 3
    hist_kernel<<<grid, THREADS, SMEM_BYTES>>>(x);
    finalize_kernel<<<(B * P64) / 256, 256>>>(wts, out);
}

// round 16
// speedup vs baseline: 1.0683x; 1.0192x over previous
#include <cuda_runtime.h>

// Histogram2d: x[32,16384,64] f32 in [0,1) -> hist[32,128,64] * weights[128,64]
//
// Two kernels: a trivial output-zero kernel, then hist. The separate
// finalize pass is GONE: hist blocks apply weights and atomicAdd(float)
// their partial counts directly into d_out. Exactness: all counts are
// integers <= 16384 < 2^24, so (float)count * 1.0-weights and their 13-way
// sums are exact and order-independent (deterministic for this dataset;
// within rel-err tolerance for any small weights).
//
// Hist mainloop identical to the 33.2us champion: 512-thread blocks
// (2 feature-halves x 8 row-offsets), NCHUNK=13 -> 416 blocks, single wave
// at occ 3 (48 warps/SM). Per-thread private u8 histograms in SMEM,
// bank-aligned: word(w,m,l) = w*1024 + m*32 + l keeps every RMW of lane l
// in bank l -> conflict-free by construction, zero atomics in the mainloop.

constexpr int B = 32, S = 16384, F = 64, BINS = 128;
constexpr int NCHUNK = 13;             // 12*1280 + 1024 = 16384
constexpr int CHUNK = 1280;            // iters = 160/128 (<=255 u8-safe, %8==0)
constexpr int THREADS = 512;           // 16 warps: fh = w&1, soff = w>>1 (0..7)
// smem: 16 warps x 1024 words. word(w, m, l) = w*1024 + m*32 + l  (bank = l)
constexpr int SMEM_BYTES = 16 * 1024 * 4;          // 65536 B -> 3 blocks/SM (48 warps)

__global__ __launch_bounds__(256)
void zero_kernel(float* __restrict__ out) {
    // 1 MB output: 256 blocks x 256 threads x 1 float4
    const int idx = blockIdx.x * 256 + threadIdx.x;
    reinterpret_cast<float4*>(out)[idx] = make_float4(0.f, 0.f, 0.f, 0.f);
}

__global__ __launch_bounds__(THREADS, 3)
void hist_kernel(const float* __restrict__ x, const float* __restrict__ wts,
                 float* __restrict__ out) {
    extern __shared__ unsigned int sh[];
    const int tid = threadIdx.x;
    const int w = tid >> 5, l = tid & 31;

    // zero own histogram: word (w, m, l) -> bank l, conflict-free, private
#pragma unroll
    for (int m = 0; m < 32; m++) sh[(w << 10) + (m << 5) + l] = 0u;

    unsigned char* sb = reinterpret_cast<unsigned char*>(sh);
    const unsigned int tbase = (w << 12) + (l << 2);   // byte base of this lane's hist

    const int fh = w & 1;        // feature half: 0 -> f 0..31, 1 -> f 32..63
    const int soff = w >> 1;     // row offset mod 8
    const int f = fh * 32 + l;
    const int b = blockIdx.y, c = blockIdx.x;

    const int row0 = c * CHUNK;
    const int rows = min(CHUNK, S - row0);   // 1280 or 1024
    const int iters = rows >> 3;             // 160 or 128 (%8==0) -> u8 safe
    const float* base = x + (((size_t)b * S + row0 + soff) * F + f);

    constexpr int U = 8;                     // load-ahead for MLP
#pragma unroll 1
    for (int i = 0; i < iters; i += U) {
        float v[U];
#pragma unroll
        for (int u = 0; u < U; u++)
            v[u] = __ldcs(base + (size_t)(i + u) * (8 * F));
#pragma unroll
        for (int u = 0; u < U; u++) {
            // exact trunc(v*128): RZ-add truncates mantissa; bin bits = [16:23)
            const unsigned int bits = __float_as_uint(__fadd_rz(v[u], 1.0f));
            // byte offset ((bin>>2)<<7) | (bin&3): keeps this lane in bank l
            const unsigned int off = (((bits >> 18) & 31u) << 7) | ((bits >> 16) & 3u);
            sb[tbase + off] = (unsigned char)(sb[tbase + off] + 1);
        }
    }
    __syncthreads();

    // Intra-block reduction over 8 row-offsets (dp4a byte extraction), then
    // weighted float REDG directly into d_out (no finalize pass). Per-bin
    // block partial <= 8*160 = 1280; batch total <= 16384 < 2^24 -> all
    // float adds exact for unit weights. Coalesced across the warp (fo).
    float* outb = out + (size_t)b * BINS * F;
#pragma unroll
    for (int k = 0; k < 4; k++) {
        const int u = tid + THREADS * k;     // 0..2047
        const int fo = u & 63;
        const int m  = u >> 6;               // -> bins 4m..4m+3
        const int fh2 = fo >> 5, fl = fo & 31;
        unsigned int s0 = 0, s1 = 0, s2 = 0, s3 = 0;
#pragma unroll
        for (int s = 0; s < 8; s++) {
            const unsigned int v = sh[((2 * s + fh2) << 10) + (m << 5) + fl];
            s0 = __dp4a(v, 0x00000001u, s0);
            s1 = __dp4a(v, 0x00000100u, s1);
            s2 = __dp4a(v, 0x00010000u, s2);
            s3 = __dp4a(v, 0x01000000u, s3);
        }
        const int e = (4 * m) * F + fo;      // element index of (bin 4m, fo)
        atomicAdd(&outb[e + 0 * F], (float)s0 * __ldg(&wts[e + 0 * F]));  // RED.F32
        atomicAdd(&outb[e + 1 * F], (float)s1 * __ldg(&wts[e + 1 * F]));
        atomicAdd(&outb[e + 2 * F], (float)s2 * __ldg(&wts[e + 2 * F]));
        atomicAdd(&outb[e + 3 * F], (float)s3 * __ldg(&wts[e + 3 * F]));
    }
}

extern "C" void kernel_launch(void* const* d_in, const int* in_sizes, int n_in,
                              void* d_out, int out_size) {
    const float* x   = (const float*)d_in[0];
    const float* wts = (const float*)d_in[1];
    float* out = (float*)d_out;

    cudaFuncSetAttribute(hist_kernel, cudaFuncAttributeMaxDynamicSharedMemorySize, SMEM_BYTES);

    zero_kernel<<<(B * BINS * F / 4) / 256, 256>>>(out);   // d_out is 0xAA-poisoned
    dim3 grid(NCHUNK, B);   // 13 x 32 = 416 blocks, single wave at occ 3
    hist_kernel<<<grid, THREADS, SMEM_BYTES>>>(x, wts, out);
}